// round 13
// baseline (speedup 1.0000x reference)
#include <cuda_runtime.h>
#include <math.h>

#define TT 64
#define WORD_V 32000
#define G 148

typedef unsigned long long ull;

__device__ __align__(16) float g_ph[32 * 256];
__device__ __align__(16) float g_pc[32 * 256];
__device__ __align__(16) float g_wh0[32 * 1024];
__device__ __align__(16) float g_wc0[32 * 1024];
__device__ __align__(16) float g_wh1[32 * 1024];
__device__ __align__(16) float g_wc1[32 * 1024];
__device__ __align__(16) float g_whist[2048 * 1024];
__device__ __align__(16) float g_ebuf[2048 * 512];
__device__ __align__(16) float g_PIH[2048 * 1024];
__device__ __align__(16) float g_WIH0[2048 * 4096];
__device__ __align__(16) float g_pbuf[4194304];
__device__ __align__(16) float g_pbufE[65536];
__device__ volatile unsigned g_flags[160];

#define PBUF_C 2097152

// flag-array grid barrier: parallel arrival stores + warp-0 poll of 148 flags.
// gen is per-CTA monotonic; base read from own slot keeps replays safe (all
// flags end every launch at the same value).
__device__ __forceinline__ void gridbar(unsigned gen, int cta, int tid) {
    __syncthreads();
    __threadfence();
    if (tid == 0) g_flags[cta] = gen;
    if (tid < 32) {
        bool done = false;
        do {
            bool ok = true;
            for (int s = tid; s < G; s += 32) ok &= (g_flags[s] >= gen);
            done = __all_sync(0xffffffffu, ok);
            if (!done) __nanosleep(128);
        } while (!done);
    }
    __syncthreads();
    __threadfence();
}

__device__ __forceinline__ float sigf(float x) { return 1.f / (1.f + expf(-x)); }

__device__ __forceinline__ ull pk2(float lo, float hi) {
    ull r; asm("mov.b64 %0, {%1, %2};" : "=l"(r) : "f"(lo), "f"(hi)); return r;
}
__device__ __forceinline__ void fma2(ull& d, ull a, ull b) {
    asm("fma.rn.f32x2 %0, %1, %2, %3;" : "=l"(d) : "l"(a), "l"(b), "l"(d));
}
__device__ __forceinline__ float2 upk(ull v) {
    float2 f; asm("mov.b64 {%0, %1}, %2;" : "=f"(f.x), "=f"(f.y) : "l"(v)); return f;
}
__device__ __forceinline__ unsigned cvt_tf32(float f) {
    unsigned u; asm("cvt.rna.tf32.f32 %0, %1;" : "=r"(u) : "f"(f)); return u;
}
__device__ __forceinline__ uint4 cvt4(float4 v) {
    return make_uint4(cvt_tf32(v.x), cvt_tf32(v.y), cvt_tf32(v.z), cvt_tf32(v.w));
}
__device__ __forceinline__ void mma_tf32(float* d, uint4 a, uint2 b) {
    asm("mma.sync.aligned.m16n8k8.row.col.f32.tf32.tf32.f32 "
        "{%0,%1,%2,%3}, {%4,%5,%6,%7}, {%8,%9}, {%0,%1,%2,%3};"
        : "+f"(d[0]), "+f"(d[1]), "+f"(d[2]), "+f"(d[3])
        : "r"(a.x), "r"(a.y), "r"(a.z), "r"(a.w), "r"(b.x), "r"(b.y));
}

// ---- tf32-MMA stage GEMM: tasks = (32 x 512 col-tile) x split-K; writes partials ----
__device__ __noinline__ void gstage_mma(
    int tid, int cta, unsigned* sXm, unsigned* sWm,
    int ncolt, int ksplit, int kc,
    const float* Xa, int Ka, const float* Wa, int lda, int cba,
    const float* Xb, int Kb, const float* Wb, int ldb, int cbb,
    int H, float* out, int ostride,
    const float* xaPart, const float* xaBias, int xaNs, int xaStride)
{
    const int lane = tid & 31, wid = tid >> 5;
    const int nb0 = wid * 64;
    const int xm = tid & 31, xq = (tid >> 5) & 3;
    const int ntasks = ncolt * ksplit;

    for (int task = cta; task < ntasks; task += G) {
        const int ct = task % ncolt, ks = task / ncolt;
        const int kbeg = ks * kc, kend = kbeg + kc;
        float acc[2][8][4];
#pragma unroll
        for (int mt = 0; mt < 2; mt++)
#pragma unroll
            for (int j = 0; j < 8; j++)
#pragma unroll
                for (int r = 0; r < 4; r++) acc[mt][j][r] = 0.f;
        int base = 0;
#pragma unroll 1
        for (int seg = 0; seg < 2; seg++) {
            const float* Xp = seg ? Xb : Xa;
            const float* Wp = seg ? Wb : Wa;
            const int K = seg ? Kb : Ka, ld = seg ? ldb : lda, cb = seg ? cbb : cba;
            if (K > 0) {
                int lo = kbeg > base ? kbeg : base;
                int hi = kend < base + K ? kend : base + K;
                if (lo < hi) {
                    const bool fuse = (seg == 0) && (xaPart != nullptr);
                    const float* xrow = fuse ? nullptr : (Xp + (size_t)xm * K);
                    const float* wp[8];
#pragma unroll
                    for (int j = 0; j < 8; j++) {
                        int i = tid + j * 256;
                        int c = i & 511, kq = i >> 9;
                        int gc = ct * 512 + c;
                        int wr = (H > 0) ? ((gc & 3) * H + (gc >> 2)) : gc;
                        wp[j] = Wp + (size_t)wr * ld + cb + kq * 4;
                    }
                    float4 rx = make_float4(0.f, 0.f, 0.f, 0.f);
                    float4 rw[8];

#define LOADX(xo)                                                                 \
    if (tid < 128) {                                                              \
        if (fuse) {                                                               \
            int col0 = (xo) + xq * 4;                                             \
            float4 s = *(const float4*)&xaBias[col0];                             \
            for (int sp = 0; sp < xaNs; sp++) {                                   \
                float4 p = __ldcg((const float4*)&xaPart[(size_t)(sp * 32 + xm) * xaStride + col0]); \
                s.x += p.x; s.y += p.y; s.z += p.z; s.w += p.w;                    \
            }                                                                     \
            rx = make_float4(tanhf(s.x), tanhf(s.y), tanhf(s.z), tanhf(s.w));     \
        } else {                                                                  \
            rx = __ldcg((const float4*)(xrow + (xo) + xq * 4));                   \
        }                                                                         \
    }
#define LOADW(xo)                                                                 \
    _Pragma("unroll")                                                             \
    for (int j = 0; j < 8; j++) rw[j] = __ldg((const float4*)(wp[j] + (xo)));

                    LOADX(lo - base);
                    LOADW(lo - base);
#pragma unroll 1
                    for (int k0 = lo; k0 < hi; k0 += 16) {
                        if (tid < 128)
                            *(uint4*)&sXm[xm * 20 + xq * 4] = cvt4(rx);
#pragma unroll
                        for (int j = 0; j < 8; j++) {
                            int i = tid + j * 256;
                            int c = i & 511, kq = i >> 9;
                            *(uint4*)&sWm[c * 20 + kq * 4] = cvt4(rw[j]);
                        }
                        __syncthreads();
                        if (k0 + 16 < hi) { LOADX(k0 + 16 - base); LOADW(k0 + 16 - base); }
#pragma unroll
                        for (int kk = 0; kk < 2; kk++) {
                            int kb = kk * 8 + (lane & 3);
                            uint4 af[2];
#pragma unroll
                            for (int mt = 0; mt < 2; mt++) {
                                int r0 = mt * 16 + (lane >> 2);
                                af[mt].x = sXm[r0 * 20 + kb];
                                af[mt].y = sXm[(r0 + 8) * 20 + kb];
                                af[mt].z = sXm[r0 * 20 + kb + 4];
                                af[mt].w = sXm[(r0 + 8) * 20 + kb + 4];
                            }
#pragma unroll
                            for (int j = 0; j < 8; j++) {
                                int n = nb0 + j * 8 + (lane >> 2);
                                uint2 bf = make_uint2(sWm[n * 20 + kb], sWm[n * 20 + kb + 4]);
                                mma_tf32(acc[0][j], af[0], bf);
                                mma_tf32(acc[1][j], af[1], bf);
                            }
                        }
                        __syncthreads();
                    }
#undef LOADX
#undef LOADW
                }
            }
            base += K;
        }
#pragma unroll
        for (int mt = 0; mt < 2; mt++) {
            int row = mt * 16 + (lane >> 2);
#pragma unroll
            for (int j = 0; j < 8; j++) {
                int col = ct * 512 + nb0 + j * 8 + (lane & 3) * 2;
                *(float2*)&out[(size_t)(ks * 32 + row) * ostride + col] =
                    make_float2(acc[mt][j][0], acc[mt][j][1]);
                *(float2*)&out[(size_t)(ks * 32 + row + 8) * ostride + col] =
                    make_float2(acc[mt][j][2], acc[mt][j][3]);
            }
        }
    }
}

// ---- small fp32 f32x2 stage (stage E only: lastp partials, K=256) ----
__device__ __noinline__ void gstage_e(
    int tid, int cta, float* sX, float* sW,
    int ksplit, int kc, const float* Xa, int Ka, const float* Wa, int lda,
    float* out, int ostride)
{
    constexpr int WSTR = 264;
    const int rg = tid / 32, cg = tid % 32;
    const int xm = tid & 31, xq = (tid >> 5) & 3;
    for (int task = cta; task < ksplit; task += G) {
        const int lo = task * kc, hi = lo + kc;
        ull acc[4][4];
#pragma unroll
        for (int r = 0; r < 4; r++)
#pragma unroll
            for (int c = 0; c < 4; c++) acc[r][c] = 0ull;
        const float* xrow = Xa + (size_t)xm * Ka;
        const float* wp[4];
#pragma unroll
        for (int j = 0; j < 4; j++) {
            int i = tid + j * 256;
            int c = i & 255, kq = i >> 8;
            wp[j] = Wa + (size_t)c * lda + kq * 4;
        }
#pragma unroll 1
        for (int k0 = lo; k0 < hi; k0 += 16) {
            if (tid < 128) {
                float4 v = __ldcg((const float4*)(xrow + k0 + xq * 4));
                sX[(xq * 4 + 0) * 36 + xm] = v.x; sX[(xq * 4 + 1) * 36 + xm] = v.y;
                sX[(xq * 4 + 2) * 36 + xm] = v.z; sX[(xq * 4 + 3) * 36 + xm] = v.w;
            }
#pragma unroll
            for (int j = 0; j < 4; j++) {
                int i = tid + j * 256;
                int c = i & 255, kq4 = (i >> 8) * 4;
                float4 v = __ldg((const float4*)(wp[j] + k0));
                sW[(kq4 + 0) * WSTR + c] = v.x; sW[(kq4 + 1) * WSTR + c] = v.y;
                sW[(kq4 + 2) * WSTR + c] = v.z; sW[(kq4 + 3) * WSTR + c] = v.w;
            }
            __syncthreads();
#pragma unroll
            for (int k = 0; k < 16; k++) {
                float4 a = *(const float4*)&sX[k * 36 + rg * 4];
                const float* br = &sW[k * WSTR + cg * 8];
                float4 b0 = *(const float4*)br, b1 = *(const float4*)(br + 4);
                ull bp0 = pk2(b0.x, b0.y), bp1 = pk2(b0.z, b0.w);
                ull bp2 = pk2(b1.x, b1.y), bp3 = pk2(b1.z, b1.w);
                float av[4] = {a.x, a.y, a.z, a.w};
#pragma unroll
                for (int r = 0; r < 4; r++) {
                    ull ad = pk2(av[r], av[r]);
                    fma2(acc[r][0], ad, bp0);
                    fma2(acc[r][1], ad, bp1);
                    fma2(acc[r][2], ad, bp2);
                    fma2(acc[r][3], ad, bp3);
                }
            }
            __syncthreads();
        }
#pragma unroll
        for (int r = 0; r < 4; r++) {
            float2 p0 = upk(acc[r][0]), p1 = upk(acc[r][1]);
            float2 p2 = upk(acc[r][2]), p3 = upk(acc[r][3]);
            float* op = &out[(size_t)(task * 32 + rg * 4 + r) * ostride + cg * 8];
            *(float4*)op = make_float4(p0.x, p0.y, p1.x, p1.y);
            *(float4*)(op + 4) = make_float4(p2.x, p2.y, p3.x, p3.y);
        }
    }
}

__global__ void __launch_bounds__(256, 1) k_loop(
    const float* __restrict__ w2p_W, const float* __restrict__ w2p_b,
    const float* __restrict__ p2w_W, const float* __restrict__ p2w_b,
    const float* __restrict__ p_Wih0, const float* __restrict__ p_Whh0,
    const float* __restrict__ p_bih0, const float* __restrict__ p_bhh0,
    const float* __restrict__ w_Wih0, const float* __restrict__ w_Whh0,
    const float* __restrict__ w_bih0, const float* __restrict__ w_bhh0,
    const float* __restrict__ w_Wih1, const float* __restrict__ w_Whh1,
    const float* __restrict__ w_bih1, const float* __restrict__ w_bhh1,
    const float* __restrict__ pos_proj_W, const float* __restrict__ pos_proj_b,
    float* __restrict__ pout)
{
    __shared__ unsigned shm[10880];          // sWm[512*20] + sXm[32*20]
    unsigned* sWm = shm;
    unsigned* sXm = shm + 10240;
    float* sXf = (float*)shm;                // stage E aliases
    float* sWf = (float*)(shm + 16 * 36);
    const int tid = threadIdx.x, cta = blockIdx.x;
    const int gt = cta * 256 + tid;
    unsigned barg = g_flags[cta];            // replay-safe barrier generation base

    {
        float4 z = make_float4(0.f, 0.f, 0.f, 0.f);
        if (gt < 2048) { ((float4*)g_ph)[gt] = z; ((float4*)g_pc)[gt] = z; }
        if (gt < 8192) { ((float4*)g_wh0)[gt] = z; ((float4*)g_wc0)[gt] = z;
                         ((float4*)g_wh1)[gt] = z; ((float4*)g_wc1)[gt] = z; }
    }
    gridbar(++barg, cta, tid);

    for (int t = 0; t < TT; t++) {
        // A: pbuf = wh1 @ w2p_W^T  (1024 cols, K=1024, 2x32 tasks, kc 32)
        gstage_mma(tid, cta, sXm, sWm, 2, 32, 32,
                   g_wh1, 1024, w2p_W, 1024, 0,
                   nullptr, 0, nullptr, 0, 0,
                   0, g_pbuf, 1024, nullptr, nullptr, 0, 0);
        gridbar(++barg, cta, tid);
        // C: pos gates (K = lastw 1024 fused-from-A-partials + ph 256), 2x40, kc 32
        gstage_mma(tid, cta, sXm, sWm, 2, 40, 32,
                   nullptr, 1024, p_Wih0, 1152, 128,
                   g_ph, 256, p_Whh0, 256, 0,
                   256, g_pbuf + PBUF_C, 1024, g_pbuf, w2p_b, 32, 1024);
        gridbar(++barg, cta, tid);
        // D: pos cell update (40 partials)
        for (int gid = gt; gid < 8192; gid += G * 256) {
            int m = gid >> 8, u = gid & 255;
            float4 s = __ldg((const float4*)&g_PIH[(size_t)(t * 32 + m) * 1024 + u * 4]);
#pragma unroll
            for (int ks = 0; ks < 40; ks++) {
                float4 p = __ldcg((const float4*)&g_pbuf[PBUF_C + (size_t)(ks * 32 + m) * 1024 + u * 4]);
                s.x += p.x; s.y += p.y; s.z += p.z; s.w += p.w;
            }
            float iv = sigf(s.x + __ldg(&p_bih0[u]) + __ldg(&p_bhh0[u]));
            float fv = sigf(s.y + __ldg(&p_bih0[256 + u]) + __ldg(&p_bhh0[256 + u]));
            float gv = tanhf(s.z + __ldg(&p_bih0[512 + u]) + __ldg(&p_bhh0[512 + u]));
            float ov = sigf(s.w + __ldg(&p_bih0[768 + u]) + __ldg(&p_bhh0[768 + u]));
            float c = fv * __ldcg(&g_pc[gid]) + iv * gv;
            g_pc[gid] = c; g_ph[gid] = ov * tanhf(c);
        }
        gridbar(++barg, cta, tid);
        // E: lastp partials only (CTAs 0-7) — pos logits moved to stage F spares
        gstage_e(tid, cta, sXf, sWf, 8, 32, g_ph, 256, p2w_W, 256, g_pbufE, 256);
        gridbar(++barg, cta, tid);
        // F: word LSTM0 gates (K = lastp 256 fused + wh0 1024), 8x16, kc 80;
        //    spare CTAs 128-143 emit pos logits + log_softmax (2 rows each)
        gstage_mma(tid, cta, sXm, sWm, 8, 16, 80,
                   nullptr, 256, w_Wih0, 768, 512,
                   g_wh0, 1024, w_Whh0, 1024, 0,
                   1024, g_pbuf, 4096, g_pbufE, p2w_b, 8, 256);
        if (cta >= 128 && cta < 144) {
            int half = tid >> 7, lt = tid & 127;
            int r = (cta - 128) * 2 + half;
            float* sred = (float*)shm + half * 256;
            float v = 0.f;
            if (lt < 48) {
                v = __ldg(&pos_proj_b[lt]);
                const float4* xp = (const float4*)(g_ph + r * 256);
                const float4* wp = (const float4*)(pos_proj_W + lt * 256);
#pragma unroll 8
                for (int k = 0; k < 64; k++) {
                    float4 x = __ldcg(xp + k), w = __ldg(wp + k);
                    v = fmaf(x.x, w.x, v); v = fmaf(x.y, w.y, v);
                    v = fmaf(x.z, w.z, v); v = fmaf(x.w, w.w, v);
                }
                sred[lt] = v;
            }
            __syncthreads();
            if (lt == 0) {
                float mx = -1e30f;
                for (int k = 0; k < 48; k++) mx = fmaxf(mx, sred[k]);
                float sm = 0.f;
                for (int k = 0; k < 48; k++) sm += expf(sred[k] - mx);
                sred[48] = mx + logf(sm);
            }
            __syncthreads();
            if (lt < 48) pout[((size_t)t * 32 + r) * 48 + lt] = v - sred[48];
        }
        gridbar(++barg, cta, tid);
        // G: word LSTM0 cell
        for (int gid = gt; gid < 32768; gid += G * 256) {
            int m = gid >> 10, u = gid & 1023;
            float4 s = __ldg((const float4*)&g_WIH0[(size_t)(t * 32 + m) * 4096 + u * 4]);
#pragma unroll
            for (int ks = 0; ks < 16; ks++) {
                float4 p = __ldcg((const float4*)&g_pbuf[(size_t)(ks * 32 + m) * 4096 + u * 4]);
                s.x += p.x; s.y += p.y; s.z += p.z; s.w += p.w;
            }
            float iv = sigf(s.x + __ldg(&w_bih0[u]) + __ldg(&w_bhh0[u]));
            float fv = sigf(s.y + __ldg(&w_bih0[1024 + u]) + __ldg(&w_bhh0[1024 + u]));
            float gv = tanhf(s.z + __ldg(&w_bih0[2048 + u]) + __ldg(&w_bhh0[2048 + u]));
            float ov = sigf(s.w + __ldg(&w_bih0[3072 + u]) + __ldg(&w_bhh0[3072 + u]));
            float c = fv * __ldcg(&g_wc0[gid]) + iv * gv;
            g_wc0[gid] = c; g_wh0[gid] = ov * tanhf(c);
        }
        gridbar(++barg, cta, tid);
        // H: word LSTM1 gates (K = wh0 1024 + wh1 1024), 8x16, kc 128
        gstage_mma(tid, cta, sXm, sWm, 8, 16, 128,
                   g_wh0, 1024, w_Wih1, 1024, 0,
                   g_wh1, 1024, w_Whh1, 1024, 0,
                   1024, g_pbuf, 4096, nullptr, nullptr, 0, 0);
        gridbar(++barg, cta, tid);
        // I: word LSTM1 cell (+ history store for hoisted e GEMM)
        for (int gid = gt; gid < 32768; gid += G * 256) {
            int m = gid >> 10, u = gid & 1023;
            float4 s = make_float4(0.f, 0.f, 0.f, 0.f);
#pragma unroll
            for (int ks = 0; ks < 16; ks++) {
                float4 p = __ldcg((const float4*)&g_pbuf[(size_t)(ks * 32 + m) * 4096 + u * 4]);
                s.x += p.x; s.y += p.y; s.z += p.z; s.w += p.w;
            }
            float iv = sigf(s.x + __ldg(&w_bih1[u]) + __ldg(&w_bhh1[u]));
            float fv = sigf(s.y + __ldg(&w_bih1[1024 + u]) + __ldg(&w_bhh1[1024 + u]));
            float gv = tanhf(s.z + __ldg(&w_bih1[2048 + u]) + __ldg(&w_bhh1[2048 + u]));
            float ov = sigf(s.w + __ldg(&w_bih1[3072 + u]) + __ldg(&w_bhh1[3072 + u]));
            float c = fv * __ldcg(&g_wc1[gid]) + iv * gv;
            g_wc1[gid] = c;
            float h = ov * tanhf(c);
            g_wh1[gid] = h;
            g_whist[(size_t)t * 32768 + gid] = h;
        }
        gridbar(++barg, cta, tid);
    }
}

// ---- generic tf32 mma GEMM: out[2048][N] = A(gather?) @ Wrow(map)^T (+bias) ----
__global__ void __launch_bounds__(256, 2) k_mmagen(
    const int* __restrict__ idx, const float* __restrict__ A, int K,
    const float* __restrict__ W, int ldW, int H,
    const float* __restrict__ bias, float* __restrict__ out, int N)
{
    __shared__ unsigned sA[64 * 36];
    __shared__ unsigned sB[128 * 36];
    const int tid = threadIdx.x, lane = tid & 31, wid = tid >> 5;
    const int wm = wid & 1, wn = wid >> 1;
    const int mb = blockIdx.y * 64, nb = blockIdx.x * 128;

    float acc[2][4][4];
#pragma unroll
    for (int mt = 0; mt < 2; mt++)
#pragma unroll
        for (int j = 0; j < 4; j++)
#pragma unroll
            for (int r = 0; r < 4; r++) acc[mt][j][r] = 0.f;

    const float* aptr[2]; unsigned* sa[2];
    const float* wptr[4]; unsigned* sb[4];
#pragma unroll
    for (int j = 0; j < 2; j++) {
        int i = tid * 2 + j, m = i >> 3, kq = i & 7;
        const float* rowp = idx ? (A + (size_t)__ldg(&idx[mb + m]) * K)
                                : (A + (size_t)(mb + m) * K);
        aptr[j] = rowp + kq * 4;
        sa[j] = &sA[m * 36 + kq * 4];
    }
#pragma unroll
    for (int j = 0; j < 4; j++) {
        int i = tid * 4 + j, n = i >> 3, kq = i & 7;
        int gc = nb + n;
        int wr = (H > 0) ? ((gc & 3) * H + (gc >> 2)) : gc;
        wptr[j] = W + (size_t)wr * ldW + kq * 4;
        sb[j] = &sB[n * 36 + kq * 4];
    }
    const int arow = wm * 32 + (lane >> 2);
    const int kcol0 = lane & 3;
    const int nrow0 = wn * 32 + (lane >> 2);

    const int nch = K / 32;
    float4 av[2], wv[4];
#define LDE(c)                                                        \
    { _Pragma("unroll") for (int j = 0; j < 2; j++) av[j] = __ldcg((const float4*)(aptr[j] + (c) * 32)); \
      _Pragma("unroll") for (int j = 0; j < 4; j++) wv[j] = __ldg((const float4*)(wptr[j] + (c) * 32)); }

    LDE(0);
#pragma unroll 1
    for (int c = 0; c < nch; c++) {
#pragma unroll
        for (int j = 0; j < 2; j++) *(uint4*)sa[j] = cvt4(av[j]);
#pragma unroll
        for (int j = 0; j < 4; j++) *(uint4*)sb[j] = cvt4(wv[j]);
        __syncthreads();
        if (c + 1 < nch) LDE(c + 1);
#pragma unroll
        for (int kk = 0; kk < 4; kk++) {
            int kc0 = kk * 8 + kcol0;
            uint4 af[2];
#pragma unroll
            for (int mt = 0; mt < 2; mt++) {
                int r0 = arow + mt * 16;
                af[mt].x = sA[r0 * 36 + kc0];
                af[mt].y = sA[(r0 + 8) * 36 + kc0];
                af[mt].z = sA[r0 * 36 + kc0 + 4];
                af[mt].w = sA[(r0 + 8) * 36 + kc0 + 4];
            }
#pragma unroll
            for (int j = 0; j < 4; j++) {
                int nr = nrow0 + j * 8;
                uint2 bf = make_uint2(sB[nr * 36 + kc0], sB[nr * 36 + kc0 + 4]);
                mma_tf32(acc[0][j], af[0], bf);
                mma_tf32(acc[1][j], af[1], bf);
            }
        }
        __syncthreads();
    }
#undef LDE

#pragma unroll
    for (int mt = 0; mt < 2; mt++) {
        int row0 = mb + wm * 32 + mt * 16 + (lane >> 2);
#pragma unroll
        for (int j = 0; j < 4; j++) {
            int col0 = nb + wn * 32 + j * 8 + (lane & 3) * 2;
            float2 bv = bias ? *(const float2*)&bias[col0] : make_float2(0.f, 0.f);
            *(float2*)&out[(size_t)row0 * N + col0] =
                make_float2(acc[mt][j][0] + bv.x, acc[mt][j][1] + bv.y);
            *(float2*)&out[(size_t)(row0 + 8) * N + col0] =
                make_float2(acc[mt][j][2] + bv.x, acc[mt][j][3] + bv.y);
        }
    }
}

__global__ void __launch_bounds__(512) k_wnorm(float* __restrict__ wout)
{
    float4* p = (float4*)(wout + (size_t)blockIdx.x * WORD_V);   // 8000 float4
    __shared__ float red[512];
    int tid = threadIdx.x;
    float m = -1e30f;
    for (int k = tid; k < 8000; k += 512) {
        float4 v = __ldcg(p + k);
        m = fmaxf(m, fmaxf(fmaxf(v.x, v.y), fmaxf(v.z, v.w)));
    }
    red[tid] = m; __syncthreads();
    for (int s = 256; s > 0; s >>= 1) { if (tid < s) red[tid] = fmaxf(red[tid], red[tid + s]); __syncthreads(); }
    m = red[0]; __syncthreads();
    float s = 0.f;
    for (int k = tid; k < 8000; k += 512) {
        float4 v = __ldcg(p + k);
        s += expf(v.x - m) + expf(v.y - m) + expf(v.z - m) + expf(v.w - m);
    }
    red[tid] = s; __syncthreads();
    for (int st = 256; st > 0; st >>= 1) { if (tid < st) red[tid] += red[tid + st]; __syncthreads(); }
    float lse = m + logf(red[0]);
    for (int k = tid; k < 8000; k += 512) {
        float4 v = __ldcg(p + k);
        p[k] = make_float4(v.x - lse, v.y - lse, v.z - lse, v.w - lse);
    }
}

extern "C" void kernel_launch(void* const* d_in, const int* in_sizes, int n_in,
                              void* d_out, int out_size)
{
    const int*   pos          = (const int*)  d_in[0];
    const int*   word         = (const int*)  d_in[1];
    const float* pos_emb_W    = (const float*)d_in[2];
    const float* word_emb_W   = (const float*)d_in[3];
    const float* w2p_W        = (const float*)d_in[4];
    const float* w2p_b        = (const float*)d_in[5];
    const float* p2w_W        = (const float*)d_in[6];
    const float* p2w_b        = (const float*)d_in[7];
    const float* p_Wih0       = (const float*)d_in[8];
    const float* p_Whh0       = (const float*)d_in[9];
    const float* p_bih0       = (const float*)d_in[10];
    const float* p_bhh0       = (const float*)d_in[11];
    const float* w_Wih0       = (const float*)d_in[12];
    const float* w_Whh0       = (const float*)d_in[13];
    const float* w_bih0       = (const float*)d_in[14];
    const float* w_bhh0       = (const float*)d_in[15];
    const float* w_Wih1       = (const float*)d_in[16];
    const float* w_Whh1       = (const float*)d_in[17];
    const float* w_bih1       = (const float*)d_in[18];
    const float* w_bhh1       = (const float*)d_in[19];
    const float* pos_proj_W   = (const float*)d_in[20];
    const float* pos_proj_b   = (const float*)d_in[21];
    const float* word_proj1_W = (const float*)d_in[22];
    const float* word_proj1_b = (const float*)d_in[23];
    const float* word_proj2_b = (const float*)d_in[24];

    float* pih = nullptr;   cudaGetSymbolAddress((void**)&pih,   g_PIH);
    float* wih = nullptr;   cudaGetSymbolAddress((void**)&wih,   g_WIH0);
    float* whist = nullptr; cudaGetSymbolAddress((void**)&whist, g_whist);
    float* ebuf = nullptr;  cudaGetSymbolAddress((void**)&ebuf,  g_ebuf);

    float* pout = (float*)d_out;
    float* wout = pout + (size_t)TT * 32 * 48;

    // hoisted input projections (token-indexed, independent of recurrence)
    k_mmagen<<<dim3(8, 32), 256>>>(pos, pos_emb_W, 128, p_Wih0, 1152, 256,
                                   nullptr, pih, 1024);
    k_mmagen<<<dim3(32, 32), 256>>>(word, word_emb_W, 512, w_Wih0, 768, 1024,
                                    nullptr, wih, 4096);

    // the whole 64-step recurrence in ONE persistent kernel
    k_loop<<<G, 256>>>(w2p_W, w2p_b, p2w_W, p2w_b,
                       p_Wih0, p_Whh0, p_bih0, p_bhh0,
                       w_Wih0, w_Whh0, w_bih0, w_bhh0,
                       w_Wih1, w_Whh1, w_bih1, w_bhh1,
                       pos_proj_W, pos_proj_b, pout);

    // hoisted e = WH1hist @ proj1^T + b, then logits GEMM, then log-softmax
    k_mmagen<<<dim3(4, 32), 256>>>(nullptr, whist, 1024, word_proj1_W, 1024, 0,
                                   word_proj1_b, ebuf, 512);
    k_mmagen<<<dim3(WORD_V / 128, 32), 256>>>(nullptr, ebuf, 512, word_emb_W, 512, 0,
                                              word_proj2_b, wout, WORD_V);
    k_wnorm<<<2048, 512>>>(wout);
}

// round 14
// speedup vs baseline: 1.2028x; 1.2028x over previous
#include <cuda_runtime.h>
#include <math.h>

#define TT 64
#define WORD_V 32000
#define G 148

typedef unsigned long long ull;

__device__ __align__(16) float g_ph[32 * 256];
__device__ __align__(16) float g_pc[32 * 256];
__device__ __align__(16) float g_wh0[32 * 1024];
__device__ __align__(16) float g_wc0[32 * 1024];
__device__ __align__(16) float g_wh1[32 * 1024];
__device__ __align__(16) float g_wc1[32 * 1024];
__device__ __align__(16) float g_whist[2048 * 1024];
__device__ __align__(16) float g_ebuf[2048 * 512];
__device__ __align__(16) float g_PIH[2048 * 1024];
__device__ __align__(16) float g_WIH0[2048 * 4096];
__device__ __align__(16) float g_pbuf[4194304];
__device__ __align__(16) float g_pbufE[65536];
__device__ unsigned g_cnt;
__device__ volatile unsigned g_gen;

#define PBUF_C 2097152

// atomic-counter grid barrier (R10 design — measured faster than flag array:
// all waiters spin on ONE hot L2 line; arrival atomics pipeline at ~1cyc/op).
__device__ __forceinline__ void gridbar() {
    __threadfence();
    __syncthreads();
    if (threadIdx.x == 0) {
        unsigned gen = g_gen;
        if (atomicAdd(&g_cnt, 1u) == G - 1) { g_cnt = 0; __threadfence(); g_gen = gen + 1; }
        else { while (g_gen == gen) { } }
    }
    __syncthreads();
}

__device__ __forceinline__ float sigf(float x) { return 1.f / (1.f + expf(-x)); }

__device__ __forceinline__ ull pk2(float lo, float hi) {
    ull r; asm("mov.b64 %0, {%1, %2};" : "=l"(r) : "f"(lo), "f"(hi)); return r;
}
__device__ __forceinline__ void fma2(ull& d, ull a, ull b) {
    asm("fma.rn.f32x2 %0, %1, %2, %3;" : "=l"(d) : "l"(a), "l"(b), "l"(d));
}
__device__ __forceinline__ float2 upk(ull v) {
    float2 f; asm("mov.b64 {%0, %1}, %2;" : "=f"(f.x), "=f"(f.y) : "l"(v)); return f;
}
__device__ __forceinline__ unsigned cvt_tf32(float f) {
    unsigned u; asm("cvt.rna.tf32.f32 %0, %1;" : "=r"(u) : "f"(f)); return u;
}
__device__ __forceinline__ uint4 cvt4(float4 v) {
    return make_uint4(cvt_tf32(v.x), cvt_tf32(v.y), cvt_tf32(v.z), cvt_tf32(v.w));
}
__device__ __forceinline__ void mma_tf32(float* d, uint4 a, uint2 b) {
    asm("mma.sync.aligned.m16n8k8.row.col.f32.tf32.tf32.f32 "
        "{%0,%1,%2,%3}, {%4,%5,%6,%7}, {%8,%9}, {%0,%1,%2,%3};"
        : "+f"(d[0]), "+f"(d[1]), "+f"(d[2]), "+f"(d[3])
        : "r"(a.x), "r"(a.y), "r"(a.z), "r"(a.w), "r"(b.x), "r"(b.y));
}

// ---- tf32-MMA stage GEMM: tasks = (32 x 512 col-tile) x split-K; writes partials ----
__device__ __noinline__ void gstage_mma(
    int tid, int cta, unsigned* sXm, unsigned* sWm,
    int ncolt, int ksplit, int kc,
    const float* Xa, int Ka, const float* Wa, int lda, int cba,
    const float* Xb, int Kb, const float* Wb, int ldb, int cbb,
    int H, float* out, int ostride,
    const float* xaPart, const float* xaBias, int xaNs, int xaStride)
{
    const int lane = tid & 31, wid = tid >> 5;
    const int nb0 = wid * 64;
    const int xm = tid & 31, xq = (tid >> 5) & 3;
    const int ntasks = ncolt * ksplit;

    for (int task = cta; task < ntasks; task += G) {
        const int ct = task % ncolt, ks = task / ncolt;
        const int kbeg = ks * kc, kend = kbeg + kc;
        float acc[2][8][4];
#pragma unroll
        for (int mt = 0; mt < 2; mt++)
#pragma unroll
            for (int j = 0; j < 8; j++)
#pragma unroll
                for (int r = 0; r < 4; r++) acc[mt][j][r] = 0.f;
        int base = 0;
#pragma unroll 1
        for (int seg = 0; seg < 2; seg++) {
            const float* Xp = seg ? Xb : Xa;
            const float* Wp = seg ? Wb : Wa;
            const int K = seg ? Kb : Ka, ld = seg ? ldb : lda, cb = seg ? cbb : cba;
            if (K > 0) {
                int lo = kbeg > base ? kbeg : base;
                int hi = kend < base + K ? kend : base + K;
                if (lo < hi) {
                    const bool fuse = (seg == 0) && (xaPart != nullptr);
                    const float* xrow = fuse ? nullptr : (Xp + (size_t)xm * K);
                    const float* wp[8];
#pragma unroll
                    for (int j = 0; j < 8; j++) {
                        int i = tid + j * 256;
                        int c = i & 511, kq = i >> 9;
                        int gc = ct * 512 + c;
                        int wr = (H > 0) ? ((gc & 3) * H + (gc >> 2)) : gc;
                        wp[j] = Wp + (size_t)wr * ld + cb + kq * 4;
                    }
                    float4 rx = make_float4(0.f, 0.f, 0.f, 0.f);
                    float4 rw[8];

#define LOADX(xo)                                                                 \
    if (tid < 128) {                                                              \
        if (fuse) {                                                               \
            int col0 = (xo) + xq * 4;                                             \
            float4 s = *(const float4*)&xaBias[col0];                             \
            for (int sp = 0; sp < xaNs; sp++) {                                   \
                float4 p = __ldcg((const float4*)&xaPart[(size_t)(sp * 32 + xm) * xaStride + col0]); \
                s.x += p.x; s.y += p.y; s.z += p.z; s.w += p.w;                    \
            }                                                                     \
            rx = make_float4(tanhf(s.x), tanhf(s.y), tanhf(s.z), tanhf(s.w));     \
        } else {                                                                  \
            rx = __ldcg((const float4*)(xrow + (xo) + xq * 4));                   \
        }                                                                         \
    }
#define LOADW(xo)                                                                 \
    _Pragma("unroll")                                                             \
    for (int j = 0; j < 8; j++) rw[j] = __ldg((const float4*)(wp[j] + (xo)));

                    LOADX(lo - base);
                    LOADW(lo - base);
#pragma unroll 1
                    for (int k0 = lo; k0 < hi; k0 += 16) {
                        if (tid < 128)
                            *(uint4*)&sXm[xm * 20 + xq * 4] = cvt4(rx);
#pragma unroll
                        for (int j = 0; j < 8; j++) {
                            int i = tid + j * 256;
                            int c = i & 511, kq = i >> 9;
                            *(uint4*)&sWm[c * 20 + kq * 4] = cvt4(rw[j]);
                        }
                        __syncthreads();
                        if (k0 + 16 < hi) { LOADX(k0 + 16 - base); LOADW(k0 + 16 - base); }
#pragma unroll
                        for (int kk = 0; kk < 2; kk++) {
                            int kb = kk * 8 + (lane & 3);
                            uint4 af[2];
#pragma unroll
                            for (int mt = 0; mt < 2; mt++) {
                                int r0 = mt * 16 + (lane >> 2);
                                af[mt].x = sXm[r0 * 20 + kb];
                                af[mt].y = sXm[(r0 + 8) * 20 + kb];
                                af[mt].z = sXm[r0 * 20 + kb + 4];
                                af[mt].w = sXm[(r0 + 8) * 20 + kb + 4];
                            }
#pragma unroll
                            for (int j = 0; j < 8; j++) {
                                int n = nb0 + j * 8 + (lane >> 2);
                                uint2 bf = make_uint2(sWm[n * 20 + kb], sWm[n * 20 + kb + 4]);
                                mma_tf32(acc[0][j], af[0], bf);
                                mma_tf32(acc[1][j], af[1], bf);
                            }
                        }
                        __syncthreads();
                    }
#undef LOADX
#undef LOADW
                }
            }
            base += K;
        }
#pragma unroll
        for (int mt = 0; mt < 2; mt++) {
            int row = mt * 16 + (lane >> 2);
#pragma unroll
            for (int j = 0; j < 8; j++) {
                int col = ct * 512 + nb0 + j * 8 + (lane & 3) * 2;
                *(float2*)&out[(size_t)(ks * 32 + row) * ostride + col] =
                    make_float2(acc[mt][j][0], acc[mt][j][1]);
                *(float2*)&out[(size_t)(ks * 32 + row + 8) * ostride + col] =
                    make_float2(acc[mt][j][2], acc[mt][j][3]);
            }
        }
    }
}

// ---- small fp32 f32x2 stage (stage E only: lastp partials, K=256) ----
__device__ __noinline__ void gstage_e(
    int tid, int cta, float* sX, float* sW,
    int ksplit, int kc, const float* Xa, int Ka, const float* Wa, int lda,
    float* out, int ostride)
{
    constexpr int WSTR = 264;
    const int rg = tid / 32, cg = tid % 32;
    const int xm = tid & 31, xq = (tid >> 5) & 3;
    for (int task = cta; task < ksplit; task += G) {
        const int lo = task * kc, hi = lo + kc;
        ull acc[4][4];
#pragma unroll
        for (int r = 0; r < 4; r++)
#pragma unroll
            for (int c = 0; c < 4; c++) acc[r][c] = 0ull;
        const float* xrow = Xa + (size_t)xm * Ka;
        const float* wp[4];
#pragma unroll
        for (int j = 0; j < 4; j++) {
            int i = tid + j * 256;
            int c = i & 255, kq = i >> 8;
            wp[j] = Wa + (size_t)c * lda + kq * 4;
        }
#pragma unroll 1
        for (int k0 = lo; k0 < hi; k0 += 16) {
            if (tid < 128) {
                float4 v = __ldcg((const float4*)(xrow + k0 + xq * 4));
                sX[(xq * 4 + 0) * 36 + xm] = v.x; sX[(xq * 4 + 1) * 36 + xm] = v.y;
                sX[(xq * 4 + 2) * 36 + xm] = v.z; sX[(xq * 4 + 3) * 36 + xm] = v.w;
            }
#pragma unroll
            for (int j = 0; j < 4; j++) {
                int i = tid + j * 256;
                int c = i & 255, kq4 = (i >> 8) * 4;
                float4 v = __ldg((const float4*)(wp[j] + k0));
                sW[(kq4 + 0) * WSTR + c] = v.x; sW[(kq4 + 1) * WSTR + c] = v.y;
                sW[(kq4 + 2) * WSTR + c] = v.z; sW[(kq4 + 3) * WSTR + c] = v.w;
            }
            __syncthreads();
#pragma unroll
            for (int k = 0; k < 16; k++) {
                float4 a = *(const float4*)&sX[k * 36 + rg * 4];
                const float* br = &sW[k * WSTR + cg * 8];
                float4 b0 = *(const float4*)br, b1 = *(const float4*)(br + 4);
                ull bp0 = pk2(b0.x, b0.y), bp1 = pk2(b0.z, b0.w);
                ull bp2 = pk2(b1.x, b1.y), bp3 = pk2(b1.z, b1.w);
                float av[4] = {a.x, a.y, a.z, a.w};
#pragma unroll
                for (int r = 0; r < 4; r++) {
                    ull ad = pk2(av[r], av[r]);
                    fma2(acc[r][0], ad, bp0);
                    fma2(acc[r][1], ad, bp1);
                    fma2(acc[r][2], ad, bp2);
                    fma2(acc[r][3], ad, bp3);
                }
            }
            __syncthreads();
        }
#pragma unroll
        for (int r = 0; r < 4; r++) {
            float2 p0 = upk(acc[r][0]), p1 = upk(acc[r][1]);
            float2 p2 = upk(acc[r][2]), p3 = upk(acc[r][3]);
            float* op = &out[(size_t)(task * 32 + rg * 4 + r) * ostride + cg * 8];
            *(float4*)op = make_float4(p0.x, p0.y, p1.x, p1.y);
            *(float4*)(op + 4) = make_float4(p2.x, p2.y, p3.x, p3.y);
        }
    }
}

__global__ void __launch_bounds__(256, 1) k_loop(
    const float* __restrict__ w2p_W, const float* __restrict__ w2p_b,
    const float* __restrict__ p2w_W, const float* __restrict__ p2w_b,
    const float* __restrict__ p_Wih0, const float* __restrict__ p_Whh0,
    const float* __restrict__ p_bih0, const float* __restrict__ p_bhh0,
    const float* __restrict__ w_Wih0, const float* __restrict__ w_Whh0,
    const float* __restrict__ w_bih0, const float* __restrict__ w_bhh0,
    const float* __restrict__ w_Wih1, const float* __restrict__ w_Whh1,
    const float* __restrict__ w_bih1, const float* __restrict__ w_bhh1,
    const float* __restrict__ pos_proj_W, const float* __restrict__ pos_proj_b,
    float* __restrict__ pout)
{
    __shared__ unsigned shm[10880];          // sWm[512*20] + sXm[32*20]
    unsigned* sWm = shm;
    unsigned* sXm = shm + 10240;
    float* sXf = (float*)shm;                // stage E aliases
    float* sWf = (float*)(shm + 16 * 36);
    const int tid = threadIdx.x, cta = blockIdx.x;
    const int gt = cta * 256 + tid;

    {
        float4 z = make_float4(0.f, 0.f, 0.f, 0.f);
        if (gt < 2048) { ((float4*)g_ph)[gt] = z; ((float4*)g_pc)[gt] = z; }
        if (gt < 8192) { ((float4*)g_wh0)[gt] = z; ((float4*)g_wc0)[gt] = z;
                         ((float4*)g_wh1)[gt] = z; ((float4*)g_wc1)[gt] = z; }
    }
    gridbar();

    for (int t = 0; t < TT; t++) {
        // A: pbuf = wh1 @ w2p_W^T  (1024 cols, K=1024, 2x32 tasks, kc 32)
        gstage_mma(tid, cta, sXm, sWm, 2, 32, 32,
                   g_wh1, 1024, w2p_W, 1024, 0,
                   nullptr, 0, nullptr, 0, 0,
                   0, g_pbuf, 1024, nullptr, nullptr, 0, 0);
        gridbar();
        // C: pos gates (K = lastw 1024 fused-from-A-partials + ph 256), 2x40, kc 32
        gstage_mma(tid, cta, sXm, sWm, 2, 40, 32,
                   nullptr, 1024, p_Wih0, 1152, 128,
                   g_ph, 256, p_Whh0, 256, 0,
                   256, g_pbuf + PBUF_C, 1024, g_pbuf, w2p_b, 32, 1024);
        gridbar();
        // D: pos cell update (40 partials)
        for (int gid = gt; gid < 8192; gid += G * 256) {
            int m = gid >> 8, u = gid & 255;
            float4 s = __ldg((const float4*)&g_PIH[(size_t)(t * 32 + m) * 1024 + u * 4]);
#pragma unroll
            for (int ks = 0; ks < 40; ks++) {
                float4 p = __ldcg((const float4*)&g_pbuf[PBUF_C + (size_t)(ks * 32 + m) * 1024 + u * 4]);
                s.x += p.x; s.y += p.y; s.z += p.z; s.w += p.w;
            }
            float iv = sigf(s.x + __ldg(&p_bih0[u]) + __ldg(&p_bhh0[u]));
            float fv = sigf(s.y + __ldg(&p_bih0[256 + u]) + __ldg(&p_bhh0[256 + u]));
            float gv = tanhf(s.z + __ldg(&p_bih0[512 + u]) + __ldg(&p_bhh0[512 + u]));
            float ov = sigf(s.w + __ldg(&p_bih0[768 + u]) + __ldg(&p_bhh0[768 + u]));
            float c = fv * __ldcg(&g_pc[gid]) + iv * gv;
            g_pc[gid] = c; g_ph[gid] = ov * tanhf(c);
        }
        gridbar();
        // E: lastp partials only (CTAs 0-7) — pos logits run on stage F's idle CTAs
        gstage_e(tid, cta, sXf, sWf, 8, 32, g_ph, 256, p2w_W, 256, g_pbufE, 256);
        gridbar();
        // F: word LSTM0 gates (K = lastp 256 fused + wh0 1024), 8x16, kc 80;
        //    spare CTAs 128-143 emit pos logits + log_softmax (2 rows each)
        gstage_mma(tid, cta, sXm, sWm, 8, 16, 80,
                   nullptr, 256, w_Wih0, 768, 512,
                   g_wh0, 1024, w_Whh0, 1024, 0,
                   1024, g_pbuf, 4096, g_pbufE, p2w_b, 8, 256);
        if (cta >= 128 && cta < 144) {
            int half = tid >> 7, lt = tid & 127;
            int r = (cta - 128) * 2 + half;
            float* sred = (float*)shm + half * 256;
            float v = 0.f;
            if (lt < 48) {
                v = __ldg(&pos_proj_b[lt]);
                const float4* xp = (const float4*)(g_ph + r * 256);
                const float4* wp = (const float4*)(pos_proj_W + lt * 256);
#pragma unroll 8
                for (int k = 0; k < 64; k++) {
                    float4 x = __ldcg(xp + k), w = __ldg(wp + k);
                    v = fmaf(x.x, w.x, v); v = fmaf(x.y, w.y, v);
                    v = fmaf(x.z, w.z, v); v = fmaf(x.w, w.w, v);
                }
                sred[lt] = v;
            }
            __syncthreads();
            if (lt == 0) {
                float mx = -1e30f;
                for (int k = 0; k < 48; k++) mx = fmaxf(mx, sred[k]);
                float sm = 0.f;
                for (int k = 0; k < 48; k++) sm += expf(sred[k] - mx);
                sred[48] = mx + logf(sm);
            }
            __syncthreads();
            if (lt < 48) pout[((size_t)t * 32 + r) * 48 + lt] = v - sred[48];
        }
        gridbar();
        // G: word LSTM0 cell
        for (int gid = gt; gid < 32768; gid += G * 256) {
            int m = gid >> 10, u = gid & 1023;
            float4 s = __ldg((const float4*)&g_WIH0[(size_t)(t * 32 + m) * 4096 + u * 4]);
#pragma unroll
            for (int ks = 0; ks < 16; ks++) {
                float4 p = __ldcg((const float4*)&g_pbuf[(size_t)(ks * 32 + m) * 4096 + u * 4]);
                s.x += p.x; s.y += p.y; s.z += p.z; s.w += p.w;
            }
            float iv = sigf(s.x + __ldg(&w_bih0[u]) + __ldg(&w_bhh0[u]));
            float fv = sigf(s.y + __ldg(&w_bih0[1024 + u]) + __ldg(&w_bhh0[1024 + u]));
            float gv = tanhf(s.z + __ldg(&w_bih0[2048 + u]) + __ldg(&w_bhh0[2048 + u]));
            float ov = sigf(s.w + __ldg(&w_bih0[3072 + u]) + __ldg(&w_bhh0[3072 + u]));
            float c = fv * __ldcg(&g_wc0[gid]) + iv * gv;
            g_wc0[gid] = c; g_wh0[gid] = ov * tanhf(c);
        }
        gridbar();
        // H: word LSTM1 gates (K = wh0 1024 + wh1 1024), 8x16, kc 128
        gstage_mma(tid, cta, sXm, sWm, 8, 16, 128,
                   g_wh0, 1024, w_Wih1, 1024, 0,
                   g_wh1, 1024, w_Whh1, 1024, 0,
                   1024, g_pbuf, 4096, nullptr, nullptr, 0, 0);
        gridbar();
        // I: word LSTM1 cell (+ history store for hoisted e GEMM)
        for (int gid = gt; gid < 32768; gid += G * 256) {
            int m = gid >> 10, u = gid & 1023;
            float4 s = make_float4(0.f, 0.f, 0.f, 0.f);
#pragma unroll
            for (int ks = 0; ks < 16; ks++) {
                float4 p = __ldcg((const float4*)&g_pbuf[(size_t)(ks * 32 + m) * 4096 + u * 4]);
                s.x += p.x; s.y += p.y; s.z += p.z; s.w += p.w;
            }
            float iv = sigf(s.x + __ldg(&w_bih1[u]) + __ldg(&w_bhh1[u]));
            float fv = sigf(s.y + __ldg(&w_bih1[1024 + u]) + __ldg(&w_bhh1[1024 + u]));
            float gv = tanhf(s.z + __ldg(&w_bih1[2048 + u]) + __ldg(&w_bhh1[2048 + u]));
            float ov = sigf(s.w + __ldg(&w_bih1[3072 + u]) + __ldg(&w_bhh1[3072 + u]));
            float c = fv * __ldcg(&g_wc1[gid]) + iv * gv;
            g_wc1[gid] = c;
            float h = ov * tanhf(c);
            g_wh1[gid] = h;
            g_whist[(size_t)t * 32768 + gid] = h;
        }
        gridbar();
    }
}

// ---- generic tf32 mma GEMM: out[2048][N] = A(gather?) @ Wrow(map)^T (+bias) ----
__global__ void __launch_bounds__(256, 2) k_mmagen(
    const int* __restrict__ idx, const float* __restrict__ A, int K,
    const float* __restrict__ W, int ldW, int H,
    const float* __restrict__ bias, float* __restrict__ out, int N)
{
    __shared__ unsigned sA[64 * 36];
    __shared__ unsigned sB[128 * 36];
    const int tid = threadIdx.x, lane = tid & 31, wid = tid >> 5;
    const int wm = wid & 1, wn = wid >> 1;
    const int mb = blockIdx.y * 64, nb = blockIdx.x * 128;

    float acc[2][4][4];
#pragma unroll
    for (int mt = 0; mt < 2; mt++)
#pragma unroll
        for (int j = 0; j < 4; j++)
#pragma unroll
            for (int r = 0; r < 4; r++) acc[mt][j][r] = 0.f;

    const float* aptr[2]; unsigned* sa[2];
    const float* wptr[4]; unsigned* sb[4];
#pragma unroll
    for (int j = 0; j < 2; j++) {
        int i = tid * 2 + j, m = i >> 3, kq = i & 7;
        const float* rowp = idx ? (A + (size_t)__ldg(&idx[mb + m]) * K)
                                : (A + (size_t)(mb + m) * K);
        aptr[j] = rowp + kq * 4;
        sa[j] = &sA[m * 36 + kq * 4];
    }
#pragma unroll
    for (int j = 0; j < 4; j++) {
        int i = tid * 4 + j, n = i >> 3, kq = i & 7;
        int gc = nb + n;
        int wr = (H > 0) ? ((gc & 3) * H + (gc >> 2)) : gc;
        wptr[j] = W + (size_t)wr * ldW + kq * 4;
        sb[j] = &sB[n * 36 + kq * 4];
    }
    const int arow = wm * 32 + (lane >> 2);
    const int kcol0 = lane & 3;
    const int nrow0 = wn * 32 + (lane >> 2);

    const int nch = K / 32;
    float4 av[2], wv[4];
#define LDE(c)                                                        \
    { _Pragma("unroll") for (int j = 0; j < 2; j++) av[j] = __ldcg((const float4*)(aptr[j] + (c) * 32)); \
      _Pragma("unroll") for (int j = 0; j < 4; j++) wv[j] = __ldg((const float4*)(wptr[j] + (c) * 32)); }

    LDE(0);
#pragma unroll 1
    for (int c = 0; c < nch; c++) {
#pragma unroll
        for (int j = 0; j < 2; j++) *(uint4*)sa[j] = cvt4(av[j]);
#pragma unroll
        for (int j = 0; j < 4; j++) *(uint4*)sb[j] = cvt4(wv[j]);
        __syncthreads();
        if (c + 1 < nch) LDE(c + 1);
#pragma unroll
        for (int kk = 0; kk < 4; kk++) {
            int kc0 = kk * 8 + kcol0;
            uint4 af[2];
#pragma unroll
            for (int mt = 0; mt < 2; mt++) {
                int r0 = arow + mt * 16;
                af[mt].x = sA[r0 * 36 + kc0];
                af[mt].y = sA[(r0 + 8) * 36 + kc0];
                af[mt].z = sA[r0 * 36 + kc0 + 4];
                af[mt].w = sA[(r0 + 8) * 36 + kc0 + 4];
            }
#pragma unroll
            for (int j = 0; j < 4; j++) {
                int nr = nrow0 + j * 8;
                uint2 bf = make_uint2(sB[nr * 36 + kc0], sB[nr * 36 + kc0 + 4]);
                mma_tf32(acc[0][j], af[0], bf);
                mma_tf32(acc[1][j], af[1], bf);
            }
        }
        __syncthreads();
    }
#undef LDE

#pragma unroll
    for (int mt = 0; mt < 2; mt++) {
        int row0 = mb + wm * 32 + mt * 16 + (lane >> 2);
#pragma unroll
        for (int j = 0; j < 4; j++) {
            int col0 = nb + wn * 32 + j * 8 + (lane & 3) * 2;
            float2 bv = bias ? *(const float2*)&bias[col0] : make_float2(0.f, 0.f);
            *(float2*)&out[(size_t)row0 * N + col0] =
                make_float2(acc[mt][j][0] + bv.x, acc[mt][j][1] + bv.y);
            *(float2*)&out[(size_t)(row0 + 8) * N + col0] =
                make_float2(acc[mt][j][2] + bv.x, acc[mt][j][3] + bv.y);
        }
    }
}

__global__ void __launch_bounds__(512) k_wnorm(float* __restrict__ wout)
{
    float4* p = (float4*)(wout + (size_t)blockIdx.x * WORD_V);   // 8000 float4
    __shared__ float red[512];
    int tid = threadIdx.x;
    float m = -1e30f;
    for (int k = tid; k < 8000; k += 512) {
        float4 v = __ldcg(p + k);
        m = fmaxf(m, fmaxf(fmaxf(v.x, v.y), fmaxf(v.z, v.w)));
    }
    red[tid] = m; __syncthreads();
    for (int s = 256; s > 0; s >>= 1) { if (tid < s) red[tid] = fmaxf(red[tid], red[tid + s]); __syncthreads(); }
    m = red[0]; __syncthreads();
    float s = 0.f;
    for (int k = tid; k < 8000; k += 512) {
        float4 v = __ldcg(p + k);
        s += expf(v.x - m) + expf(v.y - m) + expf(v.z - m) + expf(v.w - m);
    }
    red[tid] = s; __syncthreads();
    for (int st = 256; st > 0; st >>= 1) { if (tid < st) red[tid] += red[tid + st]; __syncthreads(); }
    float lse = m + logf(red[0]);
    for (int k = tid; k < 8000; k += 512) {
        float4 v = __ldcg(p + k);
        p[k] = make_float4(v.x - lse, v.y - lse, v.z - lse, v.w - lse);
    }
}

extern "C" void kernel_launch(void* const* d_in, const int* in_sizes, int n_in,
                              void* d_out, int out_size)
{
    const int*   pos          = (const int*)  d_in[0];
    const int*   word         = (const int*)  d_in[1];
    const float* pos_emb_W    = (const float*)d_in[2];
    const float* word_emb_W   = (const float*)d_in[3];
    const float* w2p_W        = (const float*)d_in[4];
    const float* w2p_b        = (const float*)d_in[5];
    const float* p2w_W        = (const float*)d_in[6];
    const float* p2w_b        = (const float*)d_in[7];
    const float* p_Wih0       = (const float*)d_in[8];
    const float* p_Whh0       = (const float*)d_in[9];
    const float* p_bih0       = (const float*)d_in[10];
    const float* p_bhh0       = (const float*)d_in[11];
    const float* w_Wih0       = (const float*)d_in[12];
    const float* w_Whh0       = (const float*)d_in[13];
    const float* w_bih0       = (const float*)d_in[14];
    const float* w_bhh0       = (const float*)d_in[15];
    const float* w_Wih1       = (const float*)d_in[16];
    const float* w_Whh1       = (const float*)d_in[17];
    const float* w_bih1       = (const float*)d_in[18];
    const float* w_bhh1       = (const float*)d_in[19];
    const float* pos_proj_W   = (const float*)d_in[20];
    const float* pos_proj_b   = (const float*)d_in[21];
    const float* word_proj1_W = (const float*)d_in[22];
    const float* word_proj1_b = (const float*)d_in[23];
    const float* word_proj2_b = (const float*)d_in[24];

    float* pih = nullptr;   cudaGetSymbolAddress((void**)&pih,   g_PIH);
    float* wih = nullptr;   cudaGetSymbolAddress((void**)&wih,   g_WIH0);
    float* whist = nullptr; cudaGetSymbolAddress((void**)&whist, g_whist);
    float* ebuf = nullptr;  cudaGetSymbolAddress((void**)&ebuf,  g_ebuf);

    float* pout = (float*)d_out;
    float* wout = pout + (size_t)TT * 32 * 48;

    // hoisted input projections (token-indexed, independent of recurrence)
    k_mmagen<<<dim3(8, 32), 256>>>(pos, pos_emb_W, 128, p_Wih0, 1152, 256,
                                   nullptr, pih, 1024);
    k_mmagen<<<dim3(32, 32), 256>>>(word, word_emb_W, 512, w_Wih0, 768, 1024,
                                    nullptr, wih, 4096);

    // the whole 64-step recurrence in ONE persistent kernel
    k_loop<<<G, 256>>>(w2p_W, w2p_b, p2w_W, p2w_b,
                       p_Wih0, p_Whh0, p_bih0, p_bhh0,
                       w_Wih0, w_Whh0, w_bih0, w_bhh0,
                       w_Wih1, w_Whh1, w_bih1, w_bhh1,
                       pos_proj_W, pos_proj_b, pout);

    // hoisted e = WH1hist @ proj1^T + b, then logits GEMM, then log-softmax
    k_mmagen<<<dim3(4, 32), 256>>>(nullptr, whist, 1024, word_proj1_W, 1024, 0,
                                   word_proj1_b, ebuf, 512);
    k_mmagen<<<dim3(WORD_V / 128, 32), 256>>>(nullptr, ebuf, 512, word_emb_W, 512, 0,
                                              word_proj2_b, wout, WORD_V);
    k_wnorm<<<2048, 512>>>(wout);
}